// round 9
// baseline (speedup 1.0000x reference)
#include <cuda_runtime.h>
#include <cstdint>

#define BB 64
#define HH 1024
#define WW 1024
#define NN 256
#define MAX_ITERS 20
#define W9 (1.0f/9.0f)

// scratch: end coords after gravity (x,y)
__device__ int2 g_end[BB * NN];

// ---------------------------------------------------------------------------
// Kernel 1: gravity_move, one warp per point, 2 warps/block.
// Interior fast path: one round of 27 aligned LDG.128 loads the 9x12 window.
// Double-buffered SMEM tile -> single syncwarp per iteration.
// ---------------------------------------------------------------------------
__global__ void __launch_bounds__(64) gravity_kernel(
    const float* __restrict__ depth, const int* __restrict__ points)
{
    const int w    = threadIdx.x >> 5;
    const int lane = threadIdx.x & 31;
    const int pidx = blockIdx.x * 2 + w;          // grid = B*N/2
    const int b    = pidx >> 8;                   // N = 256
    const float* dep = depth + (size_t)b * HH * WW;

    int2 pt = *(const int2*)(points + pidx * 2);
    int px = pt.x, py = pt.y;

    __shared__ __align__(16) float tile[2][2][128];   // [warp][buf][9x12 pitch]
    float* Tbase = &tile[w][0][0];

    // ---- loop-invariant per-lane constants ----
    // vector-load slots: lane < 27 loads row vr, segment vseg (4 floats)
    const int vr  = lane / 3, vseg = lane - vr * 3;
    const int vgo = vr * WW + vseg * 4;           // global offset from (by,bx4)
    const int vso = vr * 12 + vseg * 4;           // smem offset
    const bool vld = (lane < 27);

    // scalar border-load slots (elements lane, lane+32, lane+64 of 9x9)
    const int r0 = lane / 9,        c0 = lane - r0 * 9;
    const int e1 = lane + 32;
    const int r1 = e1 / 9,          c1 = e1 - r1 * 9;
    const int e2 = lane + 64;
    const int r2 = e2 / 9,          c2 = e2 - r2 * 9;
    const bool l3 = (lane < 17);

    // candidate cells: lane and lane+32 (cells 0..48)
    const int cA  = lane;
    const int rA  = cA / 7;
    const int dyA = rA - 3,  dxA = cA - rA * 7 - 3;
    const int cB  = lane + 32;
    const int rB  = cB / 7;
    const int dyB = rB - 3,  dxB = cB - rB * 7 - 3;
    const bool hasB = (cB < 49);
    const int sAo = (dyA + 3) * 12 + (dxA + 3);   // top-left of 3x3, pitch 12
    const int sBo = (dyB + 3) * 12 + (dxB + 3);

    for (int it = 0; it < MAX_ITERS; ++it) {
        float* T = Tbase + ((it & 1) << 7);       // alternate 128-float buffers
        const int by = py - 4, bx = px - 4;
        // interior: rows by..by+8 and cols bx4..bx4+11 all in-bounds
        const bool interior = (px >= 4) & (px <= WW - 8) &
                              (py >= 4) & (py <= HH - 5);   // warp-uniform
        int sh = 0;

        if (interior) {
            const int bx4 = bx & ~3;
            sh = bx - bx4;
            if (vld) {
                float4 v = __ldg((const float4*)(dep + by * WW + bx4 + vgo));
                *(float4*)(T + vso) = v;
            }
        } else {
            {
                int gy = by + r0, gx = bx + c0;
                T[r0 * 12 + c0] = (gy >= 0 && gy < HH && gx >= 0 && gx < WW)
                                      ? __ldg(dep + gy * WW + gx) : 0.0f;
            }
            {
                int gy = by + r1, gx = bx + c1;
                T[r1 * 12 + c1] = (gy >= 0 && gy < HH && gx >= 0 && gx < WW)
                                      ? __ldg(dep + gy * WW + gx) : 0.0f;
            }
            if (l3) {
                int gy = by + r2, gx = bx + c2;
                T[r2 * 12 + c2] = (gy >= 0 && gy < HH && gx >= 0 && gx < WW)
                                      ? __ldg(dep + gy * WW + gx) : 0.0f;
            }
        }
        __syncwarp();                              // store -> load ordering

        unsigned uA, uB = 0u;
        if (interior) {
            const float* p = T + sAo + sh;
            float a = 0.0f;
            #pragma unroll
            for (int i2 = 0; i2 < 3; ++i2)
                #pragma unroll
                for (int j2 = 0; j2 < 3; ++j2)
                    a = fmaf(p[i2 * 12 + j2], W9, a);
            unsigned ua = __float_as_uint(a);
            uA = ((int)ua >= 0) ? (ua | 0x80000000u) : ~ua;

            if (hasB) {
                const float* q = T + sBo + sh;
                float b2 = 0.0f;
                #pragma unroll
                for (int i2 = 0; i2 < 3; ++i2)
                    #pragma unroll
                    for (int j2 = 0; j2 < 3; ++j2)
                        b2 = fmaf(q[i2 * 12 + j2], W9, b2);
                unsigned ub = __float_as_uint(b2);
                uB = ((int)ub >= 0) ? (ub | 0x80000000u) : ~ub;
            }
        } else {
            {
                int yc = min(max(py + dyA, 0), HH - 1);
                int xc = min(max(px + dxA, 0), WW - 1);
                const float* p = T + (yc - by - 1) * 12 + (xc - bx - 1);
                float a = 0.0f;
                #pragma unroll
                for (int i2 = 0; i2 < 3; ++i2)
                    #pragma unroll
                    for (int j2 = 0; j2 < 3; ++j2)
                        a = fmaf(p[i2 * 12 + j2], W9, a);
                unsigned ua = __float_as_uint(a);
                uA = ((int)ua >= 0) ? (ua | 0x80000000u) : ~ua;
            }
            if (hasB) {
                int yc = min(max(py + dyB, 0), HH - 1);
                int xc = min(max(px + dxB, 0), WW - 1);
                const float* q = T + (yc - by - 1) * 12 + (xc - bx - 1);
                float b2 = 0.0f;
                #pragma unroll
                for (int i2 = 0; i2 < 3; ++i2)
                    #pragma unroll
                    for (int j2 = 0; j2 < 3; ++j2)
                        b2 = fmaf(q[i2 * 12 + j2], W9, b2);
                unsigned ub = __float_as_uint(b2);
                uB = ((int)ub >= 0) ? (ub | 0x80000000u) : ~ub;
            }
        }

        // warp argmax, exact first-index tie-break:
        // A-cells are 0..31 (== lane), B-cells 32..48 (== lane+32).
        unsigned wmax = __reduce_max_sync(0xffffffffu, max(uA, uB));
        unsigned balA = __ballot_sync(0xffffffffu, uA == wmax);
        unsigned balB = __ballot_sync(0xffffffffu, uB == wmax);
        int besti = balA ? (__ffs(balA) - 1) : (__ffs(balB) + 31);

        int rr = besti / 7;
        int ny = min(max(py + rr - 3, 0), HH - 1);
        int nx = min(max(px + besti - rr * 7 - 3, 0), WW - 1);
        bool moved = (nx != px) | (ny != py);
        px = nx; py = ny;
        if (!moved) break;                        // fixed point stays fixed
    }

    if (lane == 0) g_end[pidx] = make_int2(px, py);
}

// ---------------------------------------------------------------------------
// Kernel 2: fused resolve_overlaps + finalize + peak. One WARP per point,
// 32 blocks per batch. Pass 1: cnt + leader L. Pass 2: winner of L's overlap
// row (exact packed-key argmin). Then finalize + peak inline.
// ---------------------------------------------------------------------------
__global__ void __launch_bounds__(256) resolve_kernel(
    const float* __restrict__ depth, const int* __restrict__ points,
    float* __restrict__ out)
{
    const int w    = threadIdx.x >> 5;
    const int lane = threadIdx.x & 31;
    const int blkInBatch = blockIdx.x & 31;       // 32 blocks per batch
    const int b    = blockIdx.x >> 5;
    const int base = b * NN;

    __shared__ int ex[NN], ey[NN], sx[NN], sy[NN];
    const int t = threadIdx.x;
    {
        int2 e = g_end[base + t];
        ex[t] = e.x;  ey[t] = e.y;
        int2 s = *(const int2*)(points + (base + t) * 2);
        sx[t] = s.x;  sy[t] = s.y;
    }
    __syncthreads();

    const int i   = blkInBatch * 8 + w;
    const int exi = ex[i], eyi = ey[i];

    // ---- pass 1: overlap count + leader (first j with dist(ef_i,ef_j)<2) ----
    int cnt = 0;
    unsigned minlead = 255u;
    #pragma unroll
    for (int m = 0; m < 8; ++m) {
        int j   = lane + 32 * m;
        int ddx = exi - ex[j], ddy = eyi - ey[j];
        if (ddx * ddx + ddy * ddy < 4) {           // dist < 2.0 <=> sq < 4
            cnt++;
            minlead = min(minlead, (unsigned)j);
        }
    }
    cnt     = __reduce_add_sync(0xffffffffu, cnt);
    minlead = __reduce_min_sync(0xffffffffu, minlead);

    const bool has = (cnt > 1);
    const int  L   = (int)minlead;
    const int  exL = ex[L], eyL = ey[L];

    // ---- pass 2: winner[L] = argmin_j over ov_L of d2(sf_j, ef_L) ----
    unsigned key = 0xffffffffu;                    // (sd<<8)|j, sd < 2^21
    #pragma unroll
    for (int m = 0; m < 8; ++m) {
        int j   = lane + 32 * m;
        int ddx = exL - ex[j], ddy = eyL - ey[j];
        if (ddx * ddx + ddy * ddy < 4) {
            int sdx = sx[j] - exL, sdy = sy[j] - eyL;
            unsigned sd = (unsigned)(sdx * sdx + sdy * sdy);
            key = min(key, (sd << 8) | (unsigned)j);
        }
    }
    key = __reduce_min_sync(0xffffffffu, key);
    const int wol = (int)(key & 255u);             // winner of leader

    // ---- finalize + peak (lane 0) ----
    if (lane == 0) {
        int fx, fy;
        if (has) {
            if (i == wol) { fx = exL;   fy = eyL;   }
            else          { fx = sx[i]; fy = sy[i]; }
        } else            { fx = exi;   fy = eyi;   }

        const float* dep = depth + (size_t)b * HH * WW;
        float acc = 0.0f;
        #pragma unroll
        for (int u = -1; u <= 1; ++u)
            #pragma unroll
            for (int v = -1; v <= 1; ++v) {
                int gy = fy + u, gx = fx + v;
                float val = (gy >= 0 && gy < HH && gx >= 0 && gx < WW)
                                ? __ldg(dep + gy * WW + gx) : 0.0f;
                acc = fmaf(val, W9, acc);
            }

        out[(base + i) * 2 + 0] = (float)fx;
        out[(base + i) * 2 + 1] = (float)fy;
        out[BB * NN * 2 + base + i] = acc;
    }
}

// ---------------------------------------------------------------------------
extern "C" void kernel_launch(void* const* d_in, const int* in_sizes, int n_in,
                              void* d_out, int out_size)
{
    const float* depth  = (const float*)d_in[0];   // (64,1,1024,1024) f32
    const int*   points = (const int*)d_in[1];     // (64,256,2) i32
    float* out = (float*)d_out;                    // end (B,N,2) ++ peak (B,N)

    gravity_kernel<<<(BB * NN) / 2, 64>>>(depth, points);
    resolve_kernel<<<BB * 32, 256>>>(depth, points, out);
}

// round 10
// speedup vs baseline: 1.0122x; 1.0122x over previous
#include <cuda_runtime.h>
#include <cstdint>

#define BB 64
#define HH 1024
#define WW 1024
#define NN 256
#define MAX_ITERS 20
#define W9 (1.0f/9.0f)

// scratch
__device__ int2 g_end[BB * NN];      // end coords after gravity (x,y)
__device__ int  g_meta[BB * NN];     // winner | leader<<8 | has<<16

// ---------------------------------------------------------------------------
// Kernel 1: gravity_move, one warp per point, 2 warps/block.
// Interior fast path: one round of 27 aligned LDG.128 loads the 9x12 window.
// Double-buffered SMEM tile -> single syncwarp per iteration.
// ---------------------------------------------------------------------------
__global__ void __launch_bounds__(64) gravity_kernel(
    const float* __restrict__ depth, const int* __restrict__ points)
{
    const int w    = threadIdx.x >> 5;
    const int lane = threadIdx.x & 31;
    const int pidx = blockIdx.x * 2 + w;          // grid = B*N/2
    const int b    = pidx >> 8;                   // N = 256
    const float* dep = depth + (size_t)b * HH * WW;

    int2 pt = *(const int2*)(points + pidx * 2);
    int px = pt.x, py = pt.y;

    __shared__ __align__(16) float tile[2][2][128];   // [warp][buf][9x12 pitch]
    float* Tbase = &tile[w][0][0];

    // ---- loop-invariant per-lane constants ----
    // vector-load slots: lane < 27 loads row vr, segment vseg (4 floats)
    const int vr  = lane / 3, vseg = lane - vr * 3;
    const int vgo = vr * WW + vseg * 4;           // global offset from (by,bx4)
    const int vso = vr * 12 + vseg * 4;           // smem offset
    const bool vld = (lane < 27);

    // scalar border-load slots (elements lane, lane+32, lane+64 of 9x9)
    const int r0 = lane / 9,        c0 = lane - r0 * 9;
    const int e1 = lane + 32;
    const int r1 = e1 / 9,          c1 = e1 - r1 * 9;
    const int e2 = lane + 64;
    const int r2 = e2 / 9,          c2 = e2 - r2 * 9;
    const bool l3 = (lane < 17);

    // candidate cells: lane and lane+32 (cells 0..48)
    const int cA  = lane;
    const int rA  = cA / 7;
    const int dyA = rA - 3,  dxA = cA - rA * 7 - 3;
    const int cB  = lane + 32;
    const int rB  = cB / 7;
    const int dyB = rB - 3,  dxB = cB - rB * 7 - 3;
    const bool hasB = (cB < 49);
    const int sAo = (dyA + 3) * 12 + (dxA + 3);   // top-left of 3x3, pitch 12
    const int sBo = (dyB + 3) * 12 + (dxB + 3);

    for (int it = 0; it < MAX_ITERS; ++it) {
        float* T = Tbase + ((it & 1) << 7);       // alternate 128-float buffers
        const int by = py - 4, bx = px - 4;
        // interior: rows by..by+8 and cols bx4..bx4+11 all in-bounds
        const bool interior = (px >= 4) & (px <= WW - 8) &
                              (py >= 4) & (py <= HH - 5);   // warp-uniform
        int sh = 0;

        if (interior) {
            const int bx4 = bx & ~3;
            sh = bx - bx4;
            if (vld) {
                float4 v = __ldg((const float4*)(dep + by * WW + bx4 + vgo));
                *(float4*)(T + vso) = v;
            }
        } else {
            {
                int gy = by + r0, gx = bx + c0;
                T[r0 * 12 + c0] = (gy >= 0 && gy < HH && gx >= 0 && gx < WW)
                                      ? __ldg(dep + gy * WW + gx) : 0.0f;
            }
            {
                int gy = by + r1, gx = bx + c1;
                T[r1 * 12 + c1] = (gy >= 0 && gy < HH && gx >= 0 && gx < WW)
                                      ? __ldg(dep + gy * WW + gx) : 0.0f;
            }
            if (l3) {
                int gy = by + r2, gx = bx + c2;
                T[r2 * 12 + c2] = (gy >= 0 && gy < HH && gx >= 0 && gx < WW)
                                      ? __ldg(dep + gy * WW + gx) : 0.0f;
            }
        }
        __syncwarp();                              // store -> load ordering

        unsigned uA, uB = 0u;
        if (interior) {
            const float* p = T + sAo + sh;
            float a = 0.0f;
            #pragma unroll
            for (int i2 = 0; i2 < 3; ++i2)
                #pragma unroll
                for (int j2 = 0; j2 < 3; ++j2)
                    a = fmaf(p[i2 * 12 + j2], W9, a);
            unsigned ua = __float_as_uint(a);
            uA = ((int)ua >= 0) ? (ua | 0x80000000u) : ~ua;

            if (hasB) {
                const float* q = T + sBo + sh;
                float b2 = 0.0f;
                #pragma unroll
                for (int i2 = 0; i2 < 3; ++i2)
                    #pragma unroll
                    for (int j2 = 0; j2 < 3; ++j2)
                        b2 = fmaf(q[i2 * 12 + j2], W9, b2);
                unsigned ub = __float_as_uint(b2);
                uB = ((int)ub >= 0) ? (ub | 0x80000000u) : ~ub;
            }
        } else {
            {
                int yc = min(max(py + dyA, 0), HH - 1);
                int xc = min(max(px + dxA, 0), WW - 1);
                const float* p = T + (yc - by - 1) * 12 + (xc - bx - 1);
                float a = 0.0f;
                #pragma unroll
                for (int i2 = 0; i2 < 3; ++i2)
                    #pragma unroll
                    for (int j2 = 0; j2 < 3; ++j2)
                        a = fmaf(p[i2 * 12 + j2], W9, a);
                unsigned ua = __float_as_uint(a);
                uA = ((int)ua >= 0) ? (ua | 0x80000000u) : ~ua;
            }
            if (hasB) {
                int yc = min(max(py + dyB, 0), HH - 1);
                int xc = min(max(px + dxB, 0), WW - 1);
                const float* q = T + (yc - by - 1) * 12 + (xc - bx - 1);
                float b2 = 0.0f;
                #pragma unroll
                for (int i2 = 0; i2 < 3; ++i2)
                    #pragma unroll
                    for (int j2 = 0; j2 < 3; ++j2)
                        b2 = fmaf(q[i2 * 12 + j2], W9, b2);
                unsigned ub = __float_as_uint(b2);
                uB = ((int)ub >= 0) ? (ub | 0x80000000u) : ~ub;
            }
        }

        // warp argmax, exact first-index tie-break:
        // A-cells are 0..31 (== lane), B-cells 32..48 (== lane+32).
        unsigned wmax = __reduce_max_sync(0xffffffffu, max(uA, uB));
        unsigned balA = __ballot_sync(0xffffffffu, uA == wmax);
        unsigned balB = __ballot_sync(0xffffffffu, uB == wmax);
        int besti = balA ? (__ffs(balA) - 1) : (__ffs(balB) + 31);

        int rr = besti / 7;
        int ny = min(max(py + rr - 3, 0), HH - 1);
        int nx = min(max(px + besti - rr * 7 - 3, 0), WW - 1);
        bool moved = (nx != px) | (ny != py);
        px = nx; py = ny;
        if (!moved) break;                        // fixed point stays fixed
    }

    if (lane == 0) g_end[pidx] = make_int2(px, py);
}

// ---------------------------------------------------------------------------
// Kernel 2: pairwise overlap stats, one WARP per point (lane covers 8 j's),
// 32 blocks per batch. Packed-key REDUX reductions, exact tie-breaks.
// ---------------------------------------------------------------------------
__global__ void __launch_bounds__(256) pairwise_kernel(
    const int* __restrict__ points)
{
    const int w    = threadIdx.x >> 5;
    const int lane = threadIdx.x & 31;
    const int blkInBatch = blockIdx.x & 31;       // 32 blocks per batch
    const int b    = blockIdx.x >> 5;
    const int base = b * NN;

    __shared__ int ex[NN], ey[NN], sx[NN], sy[NN];
    const int t = threadIdx.x;
    {
        int2 e = g_end[base + t];
        ex[t] = e.x;  ey[t] = e.y;
        int2 s = *(const int2*)(points + (base + t) * 2);
        sx[t] = s.x;  sy[t] = s.y;
    }
    __syncthreads();

    const int i   = blkInBatch * 8 + w;
    const int exi = ex[i], eyi = ey[i];

    int cnt = 0;
    unsigned minlead = 255u;
    unsigned key = 0xffffffffu;                    // (sd<<8)|j, sd < 2^21

    #pragma unroll
    for (int m = 0; m < 8; ++m) {
        int j   = lane + 32 * m;
        int ddx = exi - ex[j], ddy = eyi - ey[j];
        int de  = ddx * ddx + ddy * ddy;
        if (de < 4) {                              // dist < 2.0 <=> sq < 4
            cnt++;
            minlead = min(minlead, (unsigned)j);   // argmax(ov) = first True
            int sdx = sx[j] - exi, sdy = sy[j] - eyi;
            unsigned sd = (unsigned)(sdx * sdx + sdy * sdy);
            key = min(key, (sd << 8) | (unsigned)j);
        }
    }
    cnt     = __reduce_add_sync(0xffffffffu, cnt);
    minlead = __reduce_min_sync(0xffffffffu, minlead);
    key     = __reduce_min_sync(0xffffffffu, key);

    if (lane == 0)
        g_meta[base + i] = (int)(key & 255u) | ((int)minlead << 8) | ((cnt > 1) << 16);
}

// ---------------------------------------------------------------------------
// Kernel 3: finalize coordinates + peak (exact row-major 3x3 fma chain).
// ---------------------------------------------------------------------------
__global__ void __launch_bounds__(128) finalize_kernel(
    const float* __restrict__ depth, const int* __restrict__ points,
    float* __restrict__ out)
{
    const int gid  = blockIdx.x * 128 + threadIdx.x;   // 0..16383
    const int b    = gid >> 8;
    const int base = b * NN;
    const int i    = gid & 255;

    const int meta   = g_meta[gid];
    const int leader = (meta >> 8) & 0xff;
    const bool has   = (meta >> 16) & 1;
    const int wol    = g_meta[base + leader] & 0xff;   // winner[leader]

    int fx, fy;
    if (has) {
        if (i == wol) {
            int2 e = g_end[base + leader];
            fx = e.x; fy = e.y;
        } else {
            int2 s = *(const int2*)(points + gid * 2);
            fx = s.x; fy = s.y;
        }
    } else {
        int2 e = g_end[gid];
        fx = e.x; fy = e.y;
    }

    const float* dep = depth + (size_t)b * HH * WW;
    float acc = 0.0f;
    #pragma unroll
    for (int u = -1; u <= 1; ++u)
        #pragma unroll
        for (int v = -1; v <= 1; ++v) {
            int gy = fy + u, gx = fx + v;
            float val = (gy >= 0 && gy < HH && gx >= 0 && gx < WW)
                            ? __ldg(dep + gy * WW + gx) : 0.0f;
            acc = fmaf(val, W9, acc);
        }

    out[gid * 2 + 0] = (float)fx;
    out[gid * 2 + 1] = (float)fy;
    out[BB * NN * 2 + gid] = acc;
}

// ---------------------------------------------------------------------------
extern "C" void kernel_launch(void* const* d_in, const int* in_sizes, int n_in,
                              void* d_out, int out_size)
{
    const float* depth  = (const float*)d_in[0];   // (64,1,1024,1024) f32
    const int*   points = (const int*)d_in[1];     // (64,256,2) i32
    float* out = (float*)d_out;                    // end (B,N,2) ++ peak (B,N)

    gravity_kernel <<<(BB * NN) / 2, 64>>>(depth, points);
    pairwise_kernel<<<BB * 32,       256>>>(points);
    finalize_kernel<<<(BB * NN) / 128, 128>>>(depth, points, out);
}